// round 5
// baseline (speedup 1.0000x reference)
#include <cuda_runtime.h>
#include <math.h>

#define HW 65536
#define BATCH 4
#define NSEG 32
#define GCH 128
#define GPAD 140

// ---------------- static scratch ----------------
__device__ float g_qkv [(size_t)BATCH * 288 * HW];   // qkv pre-dwconv; later reused for gated FFN 'g'
__device__ float g_qkvd[(size_t)BATCH * 288 * HW];   // qkv post-dwconv (q|k|v)
__device__ float g_svpq[(size_t)BATCH * 12  * HW];   // svp_q
__device__ float g_mu  [(size_t)BATCH * HW];         // LN mean (reused LN1/LN2)
__device__ float g_rs  [(size_t)BATCH * HW];         // LN rstd
__device__ float g_ss  [BATCH * 204];
__device__ float g_gp  [NSEG * 16 * 648];
__device__ float g_M   [BATCH * 96 * 96];
__device__ float g_Aq  [288 * 96];                   // qkv_w * ln1w
__device__ float g_bq  [288];
__device__ float g_Ag  [510 * 96];                   // interleaved ffn1/ffn2 * ln2w
__device__ float g_bg  [510];

// ---------------- f32x2 helpers ----------------
__device__ __forceinline__ unsigned long long pack2(float lo, float hi) {
    unsigned long long r;
    asm("mov.b64 %0, {%1, %2};" : "=l"(r) : "f"(lo), "f"(hi));
    return r;
}
__device__ __forceinline__ void unpack2(unsigned long long v, float& lo, float& hi) {
    asm("mov.b64 {%0, %1}, %2;" : "=f"(lo), "=f"(hi) : "l"(v));
}
__device__ __forceinline__ void fma2(unsigned long long& d, unsigned long long a, unsigned long long b) {
    asm("fma.rn.f32x2 %0, %1, %2, %0;" : "+l"(d) : "l"(a), "l"(b));
}

// ---------------- prep: fold LN weights into A matrices, compute betas, zero ss ----------------
__global__ void prep_kernel(const float* __restrict__ qkv_w,
                            const float* __restrict__ n1w, const float* __restrict__ n1b,
                            const float* __restrict__ ffn1_w, const float* __restrict__ ffn2_w,
                            const float* __restrict__ n2w, const float* __restrict__ n2b,
                            float* __restrict__ Aq, float* __restrict__ bq,
                            float* __restrict__ Ag, float* __restrict__ bg,
                            float* __restrict__ ss) {
    int r = blockIdx.x;
    int k = threadIdx.x;  // 0..95
    __shared__ float red[96];
    if (r < 288) {
        float wv = qkv_w[r * 96 + k];
        Aq[r * 96 + k] = wv * n1w[k];
        red[k] = wv * n1b[k];
        __syncthreads();
        if (k == 0) { float s = 0.f; for (int j = 0; j < 96; j++) s += red[j]; bq[r] = s; }
    } else if (r < 798) {
        int c = r - 288;                 // interleaved row 0..509
        const float* W = (c & 1) ? ffn2_w : ffn1_w;
        float wv = W[(c >> 1) * 96 + k];
        Ag[c * 96 + k] = wv * n2w[k];
        red[k] = wv * n2b[k];
        __syncthreads();
        if (k == 0) { float s = 0.f; for (int j = 0; j < 96; j++) s += red[j]; bg[c] = s; }
    } else {
        for (int j = k; j < BATCH * 204; j += 96) ss[j] = 0.f;
    }
}

// ---------------- LN stats: per-pixel mean + rstd over 96 channels ----------------
__global__ void ln_stats(const float* __restrict__ x, float* __restrict__ mu,
                         float* __restrict__ rs) {
    int i = blockIdx.x * blockDim.x + threadIdx.x;
    if (i >= BATCH * HW) return;
    int b = i >> 16, pix = i & 65535;
    const float* xp = x + (long long)b * 96 * HW + pix;
    float sum = 0.f, sq = 0.f;
    #pragma unroll 8
    for (int c = 0; c < 96; c++) {
        float v = xp[(long long)c * HW];
        sum += v; sq += v * v;
    }
    float m = sum * (1.f / 96.f);
    float var = sq * (1.f / 96.f) - m * m;
    mu[i] = m;
    rs[i] = rsqrtf(var + 1e-5f);
}

// ---------------- gate math ----------------
__device__ __forceinline__ float gatef(float a, float bb) {
    float sig = 1.f / (1.f + expf(-bb));
    float gel = 0.5f * a * (1.f + erff(a * 0.70710678118654752f));
    return a * sig + bb * gel;
}

// ---------------- GEMM: C = A[M,K] @ B[K,N=65536], BM x 128 tile, BK=8, f32x2 ----------------
// EPI: 0 = plain (+optional residual), 1 = +bias, 2 = +bias then dual-gate (rows paired, writes row/2)
// lnmode: B element = (x - mu[n]) * rs[n]
template <int BM, int EPI>
__global__ __launch_bounds__(2 * BM) void gemm_k(
    const float* __restrict__ A, const float* __restrict__ B,
    const float* __restrict__ R, float* __restrict__ C,
    const float* __restrict__ bias,
    const float* __restrict__ mu, const float* __restrict__ rs,
    int M, int K,
    long long sA, long long sB, long long sR, long long sC,
    int resid, int lnmode)
{
    constexpr int NT = 2 * BM;
    A += (long long)blockIdx.z * sA;
    B += (long long)blockIdx.z * sB;
    C += (long long)blockIdx.z * sC;
    if (resid) R += (long long)blockIdx.z * sR;
    if (lnmode) { mu += (long long)blockIdx.z * HW; rs += (long long)blockIdx.z * HW; }

    const int m_base = blockIdx.y * BM;
    const int n_base = blockIdx.x * 128;
    const int tid = threadIdx.x;

    __shared__ __align__(16) float As[2][8][BM];
    __shared__ __align__(16) float Bs[2][8][128];

    const int row_a = tid >> 1;
    const int kq    = (tid & 1) * 4;
    const int tx = tid & 15;
    const int ty = tid >> 4;

    // B loader slots: 256 float4s per stage
    const int bi0 = tid;
    const int bi1 = tid + NT;
    const int kr0 = bi0 >> 5, nc0 = (bi0 & 31) * 4;
    const int kr1 = bi1 >> 5, nc1 = (bi1 & 31) * 4;
    const bool has1 = (bi1 < 256);

    float4 m40, r40, m41, r41;
    if (lnmode) {
        m40 = *(const float4*)(mu + n_base + nc0);
        r40 = *(const float4*)(rs + n_base + nc0);
        if (has1) {
            m41 = *(const float4*)(mu + n_base + nc1);
            r41 = *(const float4*)(rs + n_base + nc1);
        }
    }

    unsigned long long acc[8][4];
    #pragma unroll
    for (int i = 0; i < 8; i++)
        #pragma unroll
        for (int j = 0; j < 4; j++) acc[i][j] = 0ULL;

    const int nstages = (K + 7) >> 3;

    float ra[4];
    float4 rb0, rb1;

    auto fetchB = [&](int kb, int nc, const float4& m4, const float4& r4) -> float4 {
        if (kb >= K) return make_float4(0.f, 0.f, 0.f, 0.f);
        float4 v = *(const float4*)(B + (long long)kb * HW + n_base + nc);
        if (lnmode) {
            v.x = (v.x - m4.x) * r4.x; v.y = (v.y - m4.y) * r4.y;
            v.z = (v.z - m4.z) * r4.z; v.w = (v.w - m4.w) * r4.w;
        }
        return v;
    };

    // prologue
    {
        #pragma unroll
        for (int i = 0; i < 4; i++) {
            int kk = kq + i;
            ra[i] = (m_base + row_a < M && kk < K) ? A[(long long)(m_base + row_a) * K + kk] : 0.f;
        }
        rb0 = fetchB(kr0, nc0, m40, r40);
        if (has1) rb1 = fetchB(kr1, nc1, m41, r41);
        #pragma unroll
        for (int i = 0; i < 4; i++) As[0][kq + i][row_a] = ra[i];
        *(float4*)&Bs[0][kr0][nc0] = rb0;
        if (has1) *(float4*)&Bs[0][kr1][nc1] = rb1;
    }
    __syncthreads();

    for (int s = 0; s < nstages; s++) {
        int buf = s & 1;
        if (s + 1 < nstages) {
            int kg = (s + 1) * 8;
            #pragma unroll
            for (int i = 0; i < 4; i++) {
                int kk = kg + kq + i;
                ra[i] = (m_base + row_a < M && kk < K) ? A[(long long)(m_base + row_a) * K + kk] : 0.f;
            }
            rb0 = fetchB(kg + kr0, nc0, m40, r40);
            if (has1) rb1 = fetchB(kg + kr1, nc1, m41, r41);
        }
        #pragma unroll
        for (int kk = 0; kk < 8; kk++) {
            float4 a0 = *(const float4*)&As[buf][kk][ty * 4];
            float4 a1 = *(const float4*)&As[buf][kk][BM / 2 + ty * 4];
            float4 b0 = *(const float4*)&Bs[buf][kk][tx * 4];
            float4 b1 = *(const float4*)&Bs[buf][kk][64 + tx * 4];
            unsigned long long bb[4];
            bb[0] = pack2(b0.x, b0.y); bb[1] = pack2(b0.z, b0.w);
            bb[2] = pack2(b1.x, b1.y); bb[3] = pack2(b1.z, b1.w);
            float am[8] = {a0.x, a0.y, a0.z, a0.w, a1.x, a1.y, a1.z, a1.w};
            #pragma unroll
            for (int i = 0; i < 8; i++) {
                unsigned long long ad = pack2(am[i], am[i]);
                #pragma unroll
                for (int j = 0; j < 4; j++) fma2(acc[i][j], ad, bb[j]);
            }
        }
        if (s + 1 < nstages) {
            int nb = buf ^ 1;
            #pragma unroll
            for (int i = 0; i < 4; i++) As[nb][kq + i][row_a] = ra[i];
            *(float4*)&Bs[nb][kr0][nc0] = rb0;
            if (has1) *(float4*)&Bs[nb][kr1][nc1] = rb1;
        }
        __syncthreads();
    }

    if (EPI == 2) {
        // paired rows: (2p, 2p+1) = (p1, p2); write gate result to row mg/2
        #pragma unroll
        for (int p = 0; p < 4; p++) {
            int i0 = 2 * p;
            int row0 = (i0 < 4) ? (ty * 4 + i0) : (BM / 2 + ty * 4 + (i0 - 4));
            int mg = m_base + row0;
            if (mg >= M) continue;
            float b1v = bias[mg], b2v = bias[mg + 1];
            float p1[8], p2[8];
            unpack2(acc[i0][0], p1[0], p1[1]); unpack2(acc[i0][1], p1[2], p1[3]);
            unpack2(acc[i0][2], p1[4], p1[5]); unpack2(acc[i0][3], p1[6], p1[7]);
            unpack2(acc[i0+1][0], p2[0], p2[1]); unpack2(acc[i0+1][1], p2[2], p2[3]);
            unpack2(acc[i0+1][2], p2[4], p2[5]); unpack2(acc[i0+1][3], p2[6], p2[7]);
            float4 v0, v1;
            float g0 = gatef(p1[0]+b1v, p2[0]+b2v), g1 = gatef(p1[1]+b1v, p2[1]+b2v);
            float g2 = gatef(p1[2]+b1v, p2[2]+b2v), g3 = gatef(p1[3]+b1v, p2[3]+b2v);
            float g4 = gatef(p1[4]+b1v, p2[4]+b2v), g5 = gatef(p1[5]+b1v, p2[5]+b2v);
            float g6 = gatef(p1[6]+b1v, p2[6]+b2v), g7 = gatef(p1[7]+b1v, p2[7]+b2v);
            v0 = make_float4(g0, g1, g2, g3);
            v1 = make_float4(g4, g5, g6, g7);
            long long orow = mg >> 1;
            long long o0 = orow * HW + n_base + tx * 4;
            *(float4*)(C + o0) = v0;
            *(float4*)(C + o0 + 64) = v1;
        }
    } else {
        #pragma unroll
        for (int i = 0; i < 8; i++) {
            int row = (i < 4) ? (ty * 4 + i) : (BM / 2 + ty * 4 + (i - 4));
            int mg = m_base + row;
            if (mg >= M) continue;
            float4 v0, v1;
            unpack2(acc[i][0], v0.x, v0.y); unpack2(acc[i][1], v0.z, v0.w);
            unpack2(acc[i][2], v1.x, v1.y); unpack2(acc[i][3], v1.z, v1.w);
            if (EPI == 1) {
                float bv = bias[mg];
                v0.x += bv; v0.y += bv; v0.z += bv; v0.w += bv;
                v1.x += bv; v1.y += bv; v1.z += bv; v1.w += bv;
            }
            long long o0 = (long long)mg * HW + n_base + tx * 4;
            long long o1 = o0 + 64;
            if (resid) {
                float4 r0 = *(const float4*)(R + o0);
                float4 r1 = *(const float4*)(R + o1);
                v0.x += r0.x; v0.y += r0.y; v0.z += r0.z; v0.w += r0.w;
                v1.x += r1.x; v1.y += r1.y; v1.z += r1.z; v1.w += r1.w;
            }
            *(float4*)(C + o0) = v0;
            *(float4*)(C + o1) = v1;
        }
    }
}

// ---------------- 3x3 depthwise conv + fused sumsq (rows < 192) ----------------
__global__ void dwconv3(const float* __restrict__ in, const float* __restrict__ w,
                        float* __restrict__ out, float* __restrict__ ss) {
    int zc = blockIdx.z;                 // b*288 + c
    int c = zc % 288;
    int b = zc / 288;
    const float* src = in  + (long long)zc * HW;
    float*       dst = out + (long long)zc * HW;
    int ox = blockIdx.x * 32, oy = blockIdx.y * 8;
    __shared__ float s[10][34];
    int tid = threadIdx.y * 32 + threadIdx.x;
    for (int i = tid; i < 340; i += 256) {
        int r = i / 34, cc = i % 34;
        int gy = oy + r - 1, gx = ox + cc - 1;
        float v = 0.f;
        if (gy >= 0 && gy < 256 && gx >= 0 && gx < 256) v = src[gy * 256 + gx];
        s[r][cc] = v;
    }
    __syncthreads();
    const float* wc = w + c * 9;
    float w00 = wc[0], w01 = wc[1], w02 = wc[2];
    float w10 = wc[3], w11 = wc[4], w12 = wc[5];
    float w20 = wc[6], w21 = wc[7], w22 = wc[8];
    int tx = threadIdx.x, ty = threadIdx.y;
    float r = w00 * s[ty][tx]     + w01 * s[ty][tx + 1]     + w02 * s[ty][tx + 2]
            + w10 * s[ty + 1][tx] + w11 * s[ty + 1][tx + 1] + w12 * s[ty + 1][tx + 2]
            + w20 * s[ty + 2][tx] + w21 * s[ty + 2][tx + 1] + w22 * s[ty + 2][tx + 2];
    dst[(oy + ty) * 256 + ox + tx] = r;
    if (c < 192) {
        float v2 = r * r;
        #pragma unroll
        for (int o = 16; o > 0; o >>= 1) v2 += __shfl_down_sync(0xffffffffu, v2, o);
        if (tx == 0) atomicAdd(&ss[b * 204 + c], v2);
    }
}

// ---------------- svp 1x1 conv + fused sumsq ----------------
__global__ void svp_kernel(const float* __restrict__ fea, const float* __restrict__ w,
                           float* __restrict__ out, float* __restrict__ ss) {
    int i = blockIdx.x * blockDim.x + threadIdx.x;
    if (i >= BATCH * HW) return;
    int b = i >> 16, pix = i & 65535;
    const float* f = fea + (long long)b * 3 * HW + pix;
    float f0 = f[0], f1 = f[HW], f2 = f[2 * HW];
    float* o = out + (long long)b * 12 * HW + pix;
    float vv[12];
    #pragma unroll
    for (int r = 0; r < 12; r++) {
        vv[r] = w[r * 3] * f0 + w[r * 3 + 1] * f1 + w[r * 3 + 2] * f2;
        o[(long long)r * HW] = vv[r];
    }
    #pragma unroll
    for (int r = 0; r < 12; r++) {
        float v2 = vv[r] * vv[r];
        #pragma unroll
        for (int off = 16; off > 0; off >>= 1) v2 += __shfl_down_sync(0xffffffffu, v2, off);
        if ((threadIdx.x & 31) == 0) atomicAdd(&ss[b * 204 + 192 + r], v2);
    }
}

// ---------------- Gram partials ----------------
__global__ __launch_bounds__(672) void gram_kernel(const float* __restrict__ qkvd,
                                                   const float* __restrict__ svpq,
                                                   float* __restrict__ gp) {
    __shared__ float qs[27 * GPAD];
    __shared__ float ks[24 * GPAD];
    int seg = blockIdx.x;
    int bh  = blockIdx.y;
    int b = bh >> 2, h = bh & 3;
    int tid = threadIdx.x;
    int c = tid / 24, d = tid % 24;
    bool active = tid < 648;
    long long segoff = (long long)seg * (HW / NSEG);
    float acc = 0.f;

    for (int ch = 0; ch < HW / NSEG; ch += GCH) {
        for (int i = tid; i < 51 * (GCH / 4); i += 672) {
            int row = i / (GCH / 4), col4 = i % (GCH / 4);
            const float* src;
            float* dstb;
            if (row < 27) {
                src = (row < 24) ? qkvd + ((long long)b * 288 + h * 24 + row) * HW
                                 : svpq + ((long long)b * 12 + h * 3 + (row - 24)) * HW;
                dstb = qs + row * GPAD;
            } else {
                int rr = row - 27;
                src = qkvd + ((long long)b * 288 + 96 + h * 24 + rr) * HW;
                dstb = ks + rr * GPAD;
            }
            *(float4*)(dstb + col4 * 4) = *(const float4*)(src + segoff + ch + col4 * 4);
        }
        __syncthreads();
        if (active) {
            const float4* q4 = (const float4*)(qs + c * GPAD);
            const float4* k4 = (const float4*)(ks + d * GPAD);
            #pragma unroll 8
            for (int p = 0; p < GCH / 4; p++) {
                float4 qv = q4[p], kv = k4[p];
                acc += qv.x * kv.x + qv.y * kv.y + qv.z * kv.z + qv.w * kv.w;
            }
        }
        __syncthreads();
    }
    if (active) gp[((long long)seg * 16 + bh) * 648 + tid] = acc;
}

// ---------------- attn softmax + fold proj_out -> M[b] ----------------
__global__ void attnm_kernel(const float* __restrict__ gp, const float* __restrict__ ss,
                             const float* __restrict__ temp, const float* __restrict__ projw,
                             float* __restrict__ Mout) {
    int b = blockIdx.x;
    __shared__ float attn_s[4][27][24];
    int tid = threadIdx.x;
    if (tid < 108) {
        int h = tid / 27, c = tid % 27;
        float ssq = (c < 24) ? ss[b * 204 + h * 24 + c]
                             : ss[b * 204 + 192 + h * 3 + (c - 24)];
        float nq = fmaxf(sqrtf(ssq), 1e-12f);
        float t = temp[h];
        float row[24];
        #pragma unroll
        for (int d = 0; d < 24; d++) {
            float g = 0.f;
            for (int s = 0; s < NSEG; s++)
                g += gp[((long long)s * 16 + b * 4 + h) * 648 + c * 24 + d];
            float nk = fmaxf(sqrtf(ss[b * 204 + 96 + h * 24 + d]), 1e-12f);
            row[d] = g * t / (nq * nk);
        }
        float mx = row[0];
        #pragma unroll
        for (int d = 1; d < 24; d++) mx = fmaxf(mx, row[d]);
        float sum = 0.f;
        #pragma unroll
        for (int d = 0; d < 24; d++) { row[d] = expf(row[d] - mx); sum += row[d]; }
        float inv = 1.f / sum;
        #pragma unroll
        for (int d = 0; d < 24; d++) attn_s[h][c][d] = row[d] * inv;
    }
    __syncthreads();
    for (int e = tid; e < 96 * 96; e += blockDim.x) {
        int o = e / 96, col = e % 96;
        int h = col / 24, d = col % 24;
        float s = 0.f;
        #pragma unroll
        for (int c = 0; c < 27; c++)
            s += projw[o * 108 + h * 27 + c] * attn_s[h][c][d];
        Mout[b * 9216 + e] = s;
    }
}

// ---------------- launch ----------------
extern "C" void kernel_launch(void* const* d_in, const int* in_sizes, int n_in,
                              void* d_out, int out_size) {
    const float* x           = (const float*)d_in[0];
    const float* svp_fea     = (const float*)d_in[1];
    const float* n1w         = (const float*)d_in[2];
    const float* n1b         = (const float*)d_in[3];
    const float* qkv_w       = (const float*)d_in[4];
    const float* qkv_dw_w    = (const float*)d_in[5];
    const float* svp_w       = (const float*)d_in[6];
    const float* temperature = (const float*)d_in[7];
    const float* proj_out_w  = (const float*)d_in[8];
    const float* n2w         = (const float*)d_in[9];
    const float* n2b         = (const float*)d_in[10];
    const float* ffn1_w      = (const float*)d_in[11];
    const float* ffn2_w      = (const float*)d_in[12];
    const float* ffn_out_w   = (const float*)d_in[13];
    float* out = (float*)d_out;

    float *qkv, *qkvd, *svpq, *mu, *rs, *ss, *gp, *Mm, *Aq, *bq, *Ag, *bg;
    cudaGetSymbolAddress((void**)&qkv,  g_qkv);
    cudaGetSymbolAddress((void**)&qkvd, g_qkvd);
    cudaGetSymbolAddress((void**)&svpq, g_svpq);
    cudaGetSymbolAddress((void**)&mu,   g_mu);
    cudaGetSymbolAddress((void**)&rs,   g_rs);
    cudaGetSymbolAddress((void**)&ss,   g_ss);
    cudaGetSymbolAddress((void**)&gp,   g_gp);
    cudaGetSymbolAddress((void**)&Mm,   g_M);
    cudaGetSymbolAddress((void**)&Aq,   g_Aq);
    cudaGetSymbolAddress((void**)&bq,   g_bq);
    cudaGetSymbolAddress((void**)&Ag,   g_Ag);
    cudaGetSymbolAddress((void**)&bg,   g_bg);

    const int pixBlocks = (BATCH * HW + 255) / 256;

    // 0. fold LN weights into A matrices; zero ss
    prep_kernel<<<799, 96>>>(qkv_w, n1w, n1b, ffn1_w, ffn2_w, n2w, n2b,
                             Aq, bq, Ag, bg, ss);
    // 1. LN1 stats
    ln_stats<<<pixBlocks, 256>>>(x, mu, rs);
    // 2. qkv = Aq @ LN(x) + bq   (LN applied in B-load)
    gemm_k<96, 1><<<dim3(512, 3, BATCH), 192>>>(Aq, x, nullptr, qkv, bq, mu, rs,
        288, 96, 0, 96LL * HW, 0, 288LL * HW, 0, 1);
    // 3. depthwise 3x3 + q/k sumsq
    dwconv3<<<dim3(8, 32, BATCH * 288), dim3(32, 8)>>>(qkv, qkv_dw_w, qkvd, ss);
    // 4. svp_q + sumsq
    svp_kernel<<<pixBlocks, 256>>>(svp_fea, svp_w, svpq, ss);
    // 5. Gram partials
    gram_kernel<<<dim3(NSEG, 16), 672>>>(qkvd, svpq, gp);
    // 6. softmax + fold proj_out -> M[b]
    attnm_kernel<<<BATCH, 128>>>(gp, ss, temperature, proj_out_w, Mm);
    // 7. x2 = x + M_b @ v  -> out
    gemm_k<96, 0><<<dim3(512, 1, BATCH), 192>>>(Mm, qkvd + 192LL * HW, x, out,
        nullptr, nullptr, nullptr,
        96, 96, 9216, 288LL * HW, 96LL * HW, 96LL * HW, 1, 0);
    // 8. LN2 stats (on out)
    ln_stats<<<pixBlocks, 256>>>(out, mu, rs);
    // 9. interleaved ffn1/ffn2 GEMM with LN'd B and fused dual-gate -> g (in qkv buffer)
    gemm_k<128, 2><<<dim3(512, 4, BATCH), 256>>>(Ag, out, nullptr, qkv, bg, mu, rs,
        510, 96, 0, 96LL * HW, 0, 288LL * HW, 0, 1);
    // 10. out = out + ffn_out_w @ g
    gemm_k<96, 0><<<dim3(512, 1, BATCH), 192>>>(ffn_out_w, qkv, out, out,
        nullptr, nullptr, nullptr,
        96, 255, 0, 288LL * HW, 96LL * HW, 96LL * HW, 1, 0);
}

// round 6
// speedup vs baseline: 1.3982x; 1.3982x over previous
#include <cuda_runtime.h>
#include <math.h>

#define HW 65536
#define BATCH 4
#define NSEG 32
#define GCH 128
#define GPAD 140

// ---------------- static scratch ----------------
__device__ float g_qkv [(size_t)BATCH * 288 * HW];   // qkv pre-dwconv; later reused for gated FFN 'g'
__device__ float g_qkvd[(size_t)BATCH * 288 * HW];   // qkv post-dwconv (q|k|v)
__device__ float g_svpq[(size_t)BATCH * 12  * HW];   // svp_q
__device__ float g_mu  [(size_t)BATCH * HW];         // LN mean (reused LN1/LN2)
__device__ float g_rs  [(size_t)BATCH * HW];         // LN rstd
__device__ float g_ss  [BATCH * 204];
__device__ float g_gp  [NSEG * 16 * 648];
__device__ float g_M   [BATCH * 96 * 96];
__device__ float g_Aq  [288 * 96];                   // qkv_w * ln1w
__device__ float g_bq  [288];
__device__ float g_Ag  [510 * 96];                   // interleaved ffn1/ffn2 * ln2w
__device__ float g_bg  [510];

// ---------------- f32x2 helpers ----------------
__device__ __forceinline__ unsigned long long pack2(float lo, float hi) {
    unsigned long long r;
    asm("mov.b64 %0, {%1, %2};" : "=l"(r) : "f"(lo), "f"(hi));
    return r;
}
__device__ __forceinline__ void unpack2(unsigned long long v, float& lo, float& hi) {
    asm("mov.b64 {%0, %1}, %2;" : "=f"(lo), "=f"(hi) : "l"(v));
}
__device__ __forceinline__ void fma2(unsigned long long& d, unsigned long long a, unsigned long long b) {
    asm("fma.rn.f32x2 %0, %1, %2, %0;" : "+l"(d) : "l"(a), "l"(b));
}

// ---------------- prep: fold LN weights into A matrices, compute betas ----------------
__global__ void prep_kernel(const float* __restrict__ qkv_w,
                            const float* __restrict__ n1w, const float* __restrict__ n1b,
                            const float* __restrict__ ffn1_w, const float* __restrict__ ffn2_w,
                            const float* __restrict__ n2w, const float* __restrict__ n2b,
                            float* __restrict__ Aq, float* __restrict__ bq,
                            float* __restrict__ Ag, float* __restrict__ bg) {
    int r = blockIdx.x;
    int k = threadIdx.x;  // 0..95
    __shared__ float red[96];
    if (r < 288) {
        float wv = qkv_w[r * 96 + k];
        Aq[r * 96 + k] = wv * n1w[k];
        red[k] = wv * n1b[k];
        __syncthreads();
        if (k == 0) { float s = 0.f; for (int j = 0; j < 96; j++) s += red[j]; bq[r] = s; }
    } else {
        int c = r - 288;                 // interleaved row 0..509
        const float* W = (c & 1) ? ffn2_w : ffn1_w;
        float wv = W[(c >> 1) * 96 + k];
        Ag[c * 96 + k] = wv * n2w[k];
        red[k] = wv * n2b[k];
        __syncthreads();
        if (k == 0) { float s = 0.f; for (int j = 0; j < 96; j++) s += red[j]; bg[c] = s; }
    }
}

// ---------------- LN stats: per-pixel mean + rstd over 96 channels ----------------
__global__ void ln_stats(const float* __restrict__ x, float* __restrict__ mu,
                         float* __restrict__ rs) {
    int i = blockIdx.x * blockDim.x + threadIdx.x;
    if (i >= BATCH * HW) return;
    int b = i >> 16, pix = i & 65535;
    const float* xp = x + (long long)b * 96 * HW + pix;
    float sum = 0.f, sq = 0.f;
    #pragma unroll 8
    for (int c = 0; c < 96; c++) {
        float v = xp[(long long)c * HW];
        sum += v; sq += v * v;
    }
    float m = sum * (1.f / 96.f);
    float var = sq * (1.f / 96.f) - m * m;
    mu[i] = m;
    rs[i] = rsqrtf(var + 1e-5f);
}

// ---------------- gate math ----------------
__device__ __forceinline__ float gatef(float a, float bb) {
    float sig = 1.f / (1.f + expf(-bb));
    float gel = 0.5f * a * (1.f + erff(a * 0.70710678118654752f));
    return a * sig + bb * gel;
}

// ---------------- GEMM: C = A[M,K] @ B[K,N=65536], BM x 128 tile, BK=8, f32x2 ----------------
// Microtile: 4 rows x 8 cols per thread; thread grid 16 x (BM/4).
// EPI: 0 = plain, 1 = +bias, 2 = +bias then dual-gate (row pairs -> row/2)
// LN : B element = (B - mu[n]) * rs[n]
// RESID: C = acc + R
template <int BM, int NT, int EPI, int LN, int RESID>
__global__ __launch_bounds__(NT) void gemm_k(
    const float* __restrict__ A, const float* __restrict__ B,
    const float* __restrict__ R, float* __restrict__ C,
    const float* __restrict__ bias,
    const float* __restrict__ mu, const float* __restrict__ rs,
    int M, int K,
    long long sA, long long sB, long long sR, long long sC)
{
    A += (long long)blockIdx.z * sA;
    B += (long long)blockIdx.z * sB;
    C += (long long)blockIdx.z * sC;
    if (RESID) R += (long long)blockIdx.z * sR;
    if (LN) { mu += (long long)blockIdx.z * HW; rs += (long long)blockIdx.z * HW; }

    const int m_base = blockIdx.y * BM;
    const int n_base = blockIdx.x * 128;
    const int tid = threadIdx.x;

    __shared__ __align__(16) float As[2][8][BM];
    __shared__ __align__(16) float Bs[2][8][128];

    const int tx = tid & 15;
    const int ty = tid >> 4;
    constexpr int NL = (BM * 8) / NT;   // A floats per thread per stage

    const bool bload = tid < 256;
    const int kr = tid >> 5, nc = (tid & 31) * 4;

    float4 m4, r4;
    if (LN) {
        if (bload) {
            m4 = *(const float4*)(mu + n_base + nc);
            r4 = *(const float4*)(rs + n_base + nc);
        }
    }

    unsigned long long acc[4][4];
    #pragma unroll
    for (int i = 0; i < 4; i++)
        #pragma unroll
        for (int j = 0; j < 4; j++) acc[i][j] = 0ULL;

    const int nstages = (K + 7) >> 3;
    float ra[NL];
    float4 rb;

    // ---- fetch stage kg into registers ----
    auto fetch = [&](int kg) {
        #pragma unroll
        for (int j = 0; j < NL; j++) {
            int i = tid + j * NT;
            int kk = i / BM, row = i % BM;
            int kkg = kg + kk;
            ra[j] = (m_base + row < M && kkg < K)
                  ? A[(long long)(m_base + row) * K + kkg] : 0.f;
        }
        if (bload) {
            int kb = kg + kr;
            if (kb < K) {
                rb = *(const float4*)(B + (long long)kb * HW + n_base + nc);
                if (LN) {
                    rb.x = (rb.x - m4.x) * r4.x; rb.y = (rb.y - m4.y) * r4.y;
                    rb.z = (rb.z - m4.z) * r4.z; rb.w = (rb.w - m4.w) * r4.w;
                }
            } else {
                rb = make_float4(0.f, 0.f, 0.f, 0.f);
            }
        }
    };
    auto stash = [&](int buf) {
        #pragma unroll
        for (int j = 0; j < NL; j++) {
            int i = tid + j * NT;
            As[buf][i / BM][i % BM] = ra[j];
        }
        if (bload) *(float4*)&Bs[buf][kr][nc] = rb;
    };

    fetch(0);
    stash(0);
    __syncthreads();

    for (int s = 0; s < nstages; s++) {
        int buf = s & 1;
        if (s + 1 < nstages) fetch((s + 1) * 8);
        #pragma unroll
        for (int kk = 0; kk < 8; kk++) {
            float4 av = *(const float4*)&As[buf][kk][ty * 4];
            float4 b0 = *(const float4*)&Bs[buf][kk][tx * 4];
            float4 b1 = *(const float4*)&Bs[buf][kk][64 + tx * 4];
            unsigned long long bb0 = pack2(b0.x, b0.y), bb1 = pack2(b0.z, b0.w);
            unsigned long long bb2 = pack2(b1.x, b1.y), bb3 = pack2(b1.z, b1.w);
            float am[4] = {av.x, av.y, av.z, av.w};
            #pragma unroll
            for (int i = 0; i < 4; i++) {
                unsigned long long ad = pack2(am[i], am[i]);
                fma2(acc[i][0], ad, bb0); fma2(acc[i][1], ad, bb1);
                fma2(acc[i][2], ad, bb2); fma2(acc[i][3], ad, bb3);
            }
        }
        if (s + 1 < nstages) stash(buf ^ 1);
        __syncthreads();
    }

    if (EPI == 2) {
        // rows paired (2j = p1-row j, 2j+1 = p2-row j); gate -> C row mg/2
        #pragma unroll
        for (int p = 0; p < 2; p++) {
            int i0 = 2 * p;
            int mg = m_base + ty * 4 + i0;
            if (mg >= M) continue;
            float b1v = bias[mg], b2v = bias[mg + 1];
            float p1[8], p2[8];
            unpack2(acc[i0][0], p1[0], p1[1]);   unpack2(acc[i0][1], p1[2], p1[3]);
            unpack2(acc[i0][2], p1[4], p1[5]);   unpack2(acc[i0][3], p1[6], p1[7]);
            unpack2(acc[i0+1][0], p2[0], p2[1]); unpack2(acc[i0+1][1], p2[2], p2[3]);
            unpack2(acc[i0+1][2], p2[4], p2[5]); unpack2(acc[i0+1][3], p2[6], p2[7]);
            float4 v0, v1;
            v0.x = gatef(p1[0] + b1v, p2[0] + b2v);
            v0.y = gatef(p1[1] + b1v, p2[1] + b2v);
            v0.z = gatef(p1[2] + b1v, p2[2] + b2v);
            v0.w = gatef(p1[3] + b1v, p2[3] + b2v);
            v1.x = gatef(p1[4] + b1v, p2[4] + b2v);
            v1.y = gatef(p1[5] + b1v, p2[5] + b2v);
            v1.z = gatef(p1[6] + b1v, p2[6] + b2v);
            v1.w = gatef(p1[7] + b1v, p2[7] + b2v);
            long long o0 = (long long)(mg >> 1) * HW + n_base + tx * 4;
            *(float4*)(C + o0) = v0;
            *(float4*)(C + o0 + 64) = v1;
        }
    } else {
        #pragma unroll
        for (int i = 0; i < 4; i++) {
            int mg = m_base + ty * 4 + i;
            if (mg >= M) continue;
            float4 v0, v1;
            unpack2(acc[i][0], v0.x, v0.y); unpack2(acc[i][1], v0.z, v0.w);
            unpack2(acc[i][2], v1.x, v1.y); unpack2(acc[i][3], v1.z, v1.w);
            if (EPI == 1) {
                float bv = bias[mg];
                v0.x += bv; v0.y += bv; v0.z += bv; v0.w += bv;
                v1.x += bv; v1.y += bv; v1.z += bv; v1.w += bv;
            }
            long long o0 = (long long)mg * HW + n_base + tx * 4;
            long long o1 = o0 + 64;
            if (RESID) {
                float4 r0 = *(const float4*)(R + o0);
                float4 r1 = *(const float4*)(R + o1);
                v0.x += r0.x; v0.y += r0.y; v0.z += r0.z; v0.w += r0.w;
                v1.x += r1.x; v1.y += r1.y; v1.z += r1.z; v1.w += r1.w;
            }
            *(float4*)(C + o0) = v0;
            *(float4*)(C + o1) = v1;
        }
    }
}

// ---------------- 3x3 depthwise conv, SAME zero padding ----------------
__global__ void dwconv3(const float* __restrict__ in, const float* __restrict__ w,
                        float* __restrict__ out) {
    int zc = blockIdx.z;                 // b*288 + c
    int c = zc % 288;
    const float* src = in  + (long long)zc * HW;
    float*       dst = out + (long long)zc * HW;
    int ox = blockIdx.x * 32, oy = blockIdx.y * 8;
    __shared__ float s[10][34];
    int tid = threadIdx.y * 32 + threadIdx.x;
    for (int i = tid; i < 340; i += 256) {
        int r = i / 34, cc = i % 34;
        int gy = oy + r - 1, gx = ox + cc - 1;
        float v = 0.f;
        if (gy >= 0 && gy < 256 && gx >= 0 && gx < 256) v = src[gy * 256 + gx];
        s[r][cc] = v;
    }
    __syncthreads();
    const float* wc = w + c * 9;
    float w00 = wc[0], w01 = wc[1], w02 = wc[2];
    float w10 = wc[3], w11 = wc[4], w12 = wc[5];
    float w20 = wc[6], w21 = wc[7], w22 = wc[8];
    int tx = threadIdx.x, ty = threadIdx.y;
    float r = w00 * s[ty][tx]     + w01 * s[ty][tx + 1]     + w02 * s[ty][tx + 2]
            + w10 * s[ty + 1][tx] + w11 * s[ty + 1][tx + 1] + w12 * s[ty + 1][tx + 2]
            + w20 * s[ty + 2][tx] + w21 * s[ty + 2][tx + 1] + w22 * s[ty + 2][tx + 2];
    dst[(oy + ty) * 256 + ox + tx] = r;
}

// ---------------- svp 1x1 conv ----------------
__global__ void svp_kernel(const float* __restrict__ fea, const float* __restrict__ w,
                           float* __restrict__ out) {
    int i = blockIdx.x * blockDim.x + threadIdx.x;
    if (i >= BATCH * HW) return;
    int b = i >> 16, pix = i & 65535;
    const float* f = fea + (long long)b * 3 * HW + pix;
    float f0 = f[0], f1 = f[HW], f2 = f[2 * HW];
    float* o = out + (long long)b * 12 * HW + pix;
    #pragma unroll
    for (int r = 0; r < 12; r++)
        o[(long long)r * HW] = w[r * 3] * f0 + w[r * 3 + 1] * f1 + w[r * 3 + 2] * f2;
}

// ---------------- per-row sum of squares (for L2 norms) ----------------
__global__ void sumsq_kernel(const float* __restrict__ qkvd, const float* __restrict__ svpq,
                             float* __restrict__ ss) {
    int bid = blockIdx.x;
    int b = bid / 204, r = bid % 204;
    const float* row = (r < 192) ? qkvd + ((long long)b * 288 + r) * HW
                                 : svpq + ((long long)b * 12 + (r - 192)) * HW;
    float acc = 0.f;
    for (int i = threadIdx.x * 4; i < HW; i += blockDim.x * 4) {
        float4 v = *(const float4*)(row + i);
        acc += v.x * v.x + v.y * v.y + v.z * v.z + v.w * v.w;
    }
    __shared__ float red[256];
    red[threadIdx.x] = acc;
    __syncthreads();
    for (int st = 128; st > 0; st >>= 1) {
        if (threadIdx.x < st) red[threadIdx.x] += red[threadIdx.x + st];
        __syncthreads();
    }
    if (threadIdx.x == 0) ss[bid] = red[0];
}

// ---------------- Gram partials ----------------
__global__ __launch_bounds__(672) void gram_kernel(const float* __restrict__ qkvd,
                                                   const float* __restrict__ svpq,
                                                   float* __restrict__ gp) {
    __shared__ float qs[27 * GPAD];
    __shared__ float ks[24 * GPAD];
    int seg = blockIdx.x;
    int bh  = blockIdx.y;
    int b = bh >> 2, h = bh & 3;
    int tid = threadIdx.x;
    int c = tid / 24, d = tid % 24;
    bool active = tid < 648;
    long long segoff = (long long)seg * (HW / NSEG);
    float acc = 0.f;

    for (int ch = 0; ch < HW / NSEG; ch += GCH) {
        for (int i = tid; i < 51 * (GCH / 4); i += 672) {
            int row = i / (GCH / 4), col4 = i % (GCH / 4);
            const float* src;
            float* dstb;
            if (row < 27) {
                src = (row < 24) ? qkvd + ((long long)b * 288 + h * 24 + row) * HW
                                 : svpq + ((long long)b * 12 + h * 3 + (row - 24)) * HW;
                dstb = qs + row * GPAD;
            } else {
                int rr = row - 27;
                src = qkvd + ((long long)b * 288 + 96 + h * 24 + rr) * HW;
                dstb = ks + rr * GPAD;
            }
            *(float4*)(dstb + col4 * 4) = *(const float4*)(src + segoff + ch + col4 * 4);
        }
        __syncthreads();
        if (active) {
            const float4* q4 = (const float4*)(qs + c * GPAD);
            const float4* k4 = (const float4*)(ks + d * GPAD);
            #pragma unroll 8
            for (int p = 0; p < GCH / 4; p++) {
                float4 qv = q4[p], kv = k4[p];
                acc += qv.x * kv.x + qv.y * kv.y + qv.z * kv.z + qv.w * kv.w;
            }
        }
        __syncthreads();
    }
    if (active) gp[((long long)seg * 16 + bh) * 648 + tid] = acc;
}

// ---------------- attn softmax + fold proj_out -> M[b] ----------------
__global__ void attnm_kernel(const float* __restrict__ gp, const float* __restrict__ ss,
                             const float* __restrict__ temp, const float* __restrict__ projw,
                             float* __restrict__ Mout) {
    int b = blockIdx.x;
    __shared__ float attn_s[4][27][24];
    int tid = threadIdx.x;
    if (tid < 108) {
        int h = tid / 27, c = tid % 27;
        float ssq = (c < 24) ? ss[b * 204 + h * 24 + c]
                             : ss[b * 204 + 192 + h * 3 + (c - 24)];
        float nq = fmaxf(sqrtf(ssq), 1e-12f);
        float t = temp[h];
        float row[24];
        #pragma unroll
        for (int d = 0; d < 24; d++) {
            float g = 0.f;
            for (int s = 0; s < NSEG; s++)
                g += gp[((long long)s * 16 + b * 4 + h) * 648 + c * 24 + d];
            float nk = fmaxf(sqrtf(ss[b * 204 + 96 + h * 24 + d]), 1e-12f);
            row[d] = g * t / (nq * nk);
        }
        float mx = row[0];
        #pragma unroll
        for (int d = 1; d < 24; d++) mx = fmaxf(mx, row[d]);
        float sum = 0.f;
        #pragma unroll
        for (int d = 0; d < 24; d++) { row[d] = expf(row[d] - mx); sum += row[d]; }
        float inv = 1.f / sum;
        #pragma unroll
        for (int d = 0; d < 24; d++) attn_s[h][c][d] = row[d] * inv;
    }
    __syncthreads();
    for (int e = tid; e < 96 * 96; e += blockDim.x) {
        int o = e / 96, col = e % 96;
        int h = col / 24, d = col % 24;
        float s = 0.f;
        #pragma unroll
        for (int c = 0; c < 27; c++)
            s += projw[o * 108 + h * 27 + c] * attn_s[h][c][d];
        Mout[b * 9216 + e] = s;
    }
}

// ---------------- launch ----------------
extern "C" void kernel_launch(void* const* d_in, const int* in_sizes, int n_in,
                              void* d_out, int out_size) {
    const float* x           = (const float*)d_in[0];
    const float* svp_fea     = (const float*)d_in[1];
    const float* n1w         = (const float*)d_in[2];
    const float* n1b         = (const float*)d_in[3];
    const float* qkv_w       = (const float*)d_in[4];
    const float* qkv_dw_w    = (const float*)d_in[5];
    const float* svp_w       = (const float*)d_in[6];
    const float* temperature = (const float*)d_in[7];
    const float* proj_out_w  = (const float*)d_in[8];
    const float* n2w         = (const float*)d_in[9];
    const float* n2b         = (const float*)d_in[10];
    const float* ffn1_w      = (const float*)d_in[11];
    const float* ffn2_w      = (const float*)d_in[12];
    const float* ffn_out_w   = (const float*)d_in[13];
    float* out = (float*)d_out;

    float *qkv, *qkvd, *svpq, *mu, *rs, *ss, *gp, *Mm, *Aq, *bq, *Ag, *bg;
    cudaGetSymbolAddress((void**)&qkv,  g_qkv);
    cudaGetSymbolAddress((void**)&qkvd, g_qkvd);
    cudaGetSymbolAddress((void**)&svpq, g_svpq);
    cudaGetSymbolAddress((void**)&mu,   g_mu);
    cudaGetSymbolAddress((void**)&rs,   g_rs);
    cudaGetSymbolAddress((void**)&ss,   g_ss);
    cudaGetSymbolAddress((void**)&gp,   g_gp);
    cudaGetSymbolAddress((void**)&Mm,   g_M);
    cudaGetSymbolAddress((void**)&Aq,   g_Aq);
    cudaGetSymbolAddress((void**)&bq,   g_bq);
    cudaGetSymbolAddress((void**)&Ag,   g_Ag);
    cudaGetSymbolAddress((void**)&bg,   g_bg);

    const int pixBlocks = (BATCH * HW + 255) / 256;

    // 0. fold LN weights into A matrices
    prep_kernel<<<798, 96>>>(qkv_w, n1w, n1b, ffn1_w, ffn2_w, n2w, n2b,
                             Aq, bq, Ag, bg);
    // 1. LN1 stats
    ln_stats<<<pixBlocks, 256>>>(x, mu, rs);
    // 2. qkv = Aq @ LN(x) + bq   (LN applied in B-load)  [M=288, exact 3x96 tiles]
    gemm_k<96, 384, 1, 1, 0><<<dim3(512, 3, BATCH), 384>>>(Aq, x, nullptr, qkv, bq, mu, rs,
        288, 96, 0, 96LL * HW, 0, 288LL * HW);
    // 3. depthwise 3x3
    dwconv3<<<dim3(8, 32, BATCH * 288), dim3(32, 8)>>>(qkv, qkv_dw_w, qkvd);
    // 4. svp_q
    svp_kernel<<<pixBlocks, 256>>>(svp_fea, svp_w, svpq);
    // 5. row sums of squares
    sumsq_kernel<<<BATCH * 204, 256>>>(qkvd, svpq, ss);
    // 6. Gram partials
    gram_kernel<<<dim3(NSEG, 16), 672>>>(qkvd, svpq, gp);
    // 7. softmax + fold proj_out -> M[b]
    attnm_kernel<<<BATCH, 128>>>(gp, ss, temperature, proj_out_w, Mm);
    // 8. x2 = x + M_b @ v -> out   [M=96 exact]
    gemm_k<96, 384, 0, 0, 1><<<dim3(512, 1, BATCH), 384>>>(Mm, qkvd + 192LL * HW, x, out,
        nullptr, nullptr, nullptr,
        96, 96, 9216, 288LL * HW, 96LL * HW, 96LL * HW);
    // 9. LN2 stats (on out)
    ln_stats<<<pixBlocks, 256>>>(out, mu, rs);
    // 10. interleaved ffn1/ffn2 GEMM, LN'd B, fused dual-gate -> g (qkv buffer)
    gemm_k<128, 512, 2, 1, 0><<<dim3(512, 4, BATCH), 512>>>(Ag, out, nullptr, qkv, bg, mu, rs,
        510, 96, 0, 96LL * HW, 0, 288LL * HW);
    // 11. out = out + ffn_out_w @ g   [M=96 exact, K=255]
    gemm_k<96, 384, 0, 0, 1><<<dim3(512, 1, BATCH), 384>>>(ffn_out_w, qkv, out, out,
        nullptr, nullptr, nullptr,
        96, 255, 0, 288LL * HW, 96LL * HW, 96LL * HW);
}

// round 7
// speedup vs baseline: 1.7106x; 1.2235x over previous
#include <cuda_runtime.h>
#include <math.h>

#define HW 65536
#define BATCH 4
#define NSEG 32
#define GCH 128
#define GPAD 140

// ---------------- static scratch ----------------
__device__ float g_qkv [(size_t)BATCH * 288 * HW];   // qkv pre-dwconv; later reused for gated FFN 'g'
__device__ float g_qkvd[(size_t)BATCH * 288 * HW];   // qkv post-dwconv (q|k|v)
__device__ float g_svpq[(size_t)BATCH * 12  * HW];   // svp_q
__device__ float g_mu  [(size_t)BATCH * HW];         // LN mean (reused LN1/LN2)
__device__ float g_rs  [(size_t)BATCH * HW];         // LN rstd
__device__ float g_ss  [BATCH * 204];
__device__ float g_gp  [NSEG * 16 * 648];
__device__ float g_M   [BATCH * 96 * 96];
__device__ float g_Aq  [288 * 96];                   // qkv_w * ln1w
__device__ float g_bq  [288];
__device__ float g_Ag  [510 * 96];                   // interleaved ffn1/ffn2 * ln2w
__device__ float g_bg  [510];

// ---------------- f32x2 helpers ----------------
__device__ __forceinline__ unsigned long long pack2(float lo, float hi) {
    unsigned long long r;
    asm("mov.b64 %0, {%1, %2};" : "=l"(r) : "f"(lo), "f"(hi));
    return r;
}
__device__ __forceinline__ void unpack2(unsigned long long v, float& lo, float& hi) {
    asm("mov.b64 {%0, %1}, %2;" : "=f"(lo), "=f"(hi) : "l"(v));
}
__device__ __forceinline__ void fma2(unsigned long long& d, unsigned long long a, unsigned long long b) {
    asm("fma.rn.f32x2 %0, %1, %2, %0;" : "+l"(d) : "l"(a), "l"(b));
}

// ---------------- prep: fold LN weights into A matrices, compute betas ----------------
__global__ void prep_kernel(const float* __restrict__ qkv_w,
                            const float* __restrict__ n1w, const float* __restrict__ n1b,
                            const float* __restrict__ ffn1_w, const float* __restrict__ ffn2_w,
                            const float* __restrict__ n2w, const float* __restrict__ n2b,
                            float* __restrict__ Aq, float* __restrict__ bq,
                            float* __restrict__ Ag, float* __restrict__ bg) {
    int r = blockIdx.x;
    int k = threadIdx.x;  // 0..95
    __shared__ float red[96];
    if (r < 288) {
        float wv = qkv_w[r * 96 + k];
        Aq[r * 96 + k] = wv * n1w[k];
        red[k] = wv * n1b[k];
        __syncthreads();
        if (k == 0) { float s = 0.f; for (int j = 0; j < 96; j++) s += red[j]; bq[r] = s; }
    } else {
        int c = r - 288;                 // interleaved row 0..509
        const float* W = (c & 1) ? ffn2_w : ffn1_w;
        float wv = W[(c >> 1) * 96 + k];
        Ag[c * 96 + k] = wv * n2w[k];
        red[k] = wv * n2b[k];
        __syncthreads();
        if (k == 0) { float s = 0.f; for (int j = 0; j < 96; j++) s += red[j]; bg[c] = s; }
    }
}

// ---------------- LN stats: per-pixel mean + rstd over 96 channels ----------------
__global__ void ln_stats(const float* __restrict__ x, float* __restrict__ mu,
                         float* __restrict__ rs) {
    int i = blockIdx.x * blockDim.x + threadIdx.x;
    if (i >= BATCH * HW) return;
    int b = i >> 16, pix = i & 65535;
    const float* xp = x + (long long)b * 96 * HW + pix;
    float sum = 0.f, sq = 0.f;
    #pragma unroll 8
    for (int c = 0; c < 96; c++) {
        float v = xp[(long long)c * HW];
        sum += v; sq += v * v;
    }
    float m = sum * (1.f / 96.f);
    float var = sq * (1.f / 96.f) - m * m;
    mu[i] = m;
    rs[i] = rsqrtf(var + 1e-5f);
}

// ---------------- gate math ----------------
__device__ __forceinline__ float gatef(float a, float bb) {
    float sig = 1.f / (1.f + expf(-bb));
    float gel = 0.5f * a * (1.f + erff(a * 0.70710678118654752f));
    return a * sig + bb * gel;
}

// ---------------- GEMM: C = A[M,K] @ B[K,N=65536], BM x 256 tile, BK=8, f32x2 ----------------
// Microtile: 4 rows x 16 cols per thread; thread grid 16 x (BM/4).
// EPI: 0 = plain, 1 = +bias, 2 = +bias then dual-gate (row pairs -> row/2)
// LN : B element = (B - mu[n]) * rs[n];  RESID: C = acc + R
template <int BM, int NT, int EPI, int LN, int RESID>
__global__ __launch_bounds__(NT) void gemm_k(
    const float* __restrict__ A, const float* __restrict__ B,
    const float* __restrict__ R, float* __restrict__ C,
    const float* __restrict__ bias,
    const float* __restrict__ mu, const float* __restrict__ rs,
    int M, int K,
    long long sA, long long sB, long long sR, long long sC)
{
    constexpr int BN = 256;
    A += (long long)blockIdx.z * sA;
    B += (long long)blockIdx.z * sB;
    C += (long long)blockIdx.z * sC;
    if (RESID) R += (long long)blockIdx.z * sR;
    if (LN) { mu += (long long)blockIdx.z * HW; rs += (long long)blockIdx.z * HW; }

    const int m_base = blockIdx.y * BM;
    const int n_base = blockIdx.x * BN;
    const int tid = threadIdx.x;

    __shared__ __align__(16) float As[2][8][BM];
    __shared__ __align__(16) float Bs[2][8][BN];

    const int tx = tid & 15;
    const int ty = tid >> 4;
    constexpr int NL  = (BM * 8) / NT;          // A floats per thread per stage
    constexpr int BSL = (512 + NT - 1) / NT;    // B float4 slots per thread (512 total)

    float4 m4[BSL], r4[BSL];
    if (LN) {
        #pragma unroll
        for (int j = 0; j < BSL; j++) {
            int s = tid + j * NT;
            if (s < 512) {
                int nc = (s & 63) * 4;
                m4[j] = *(const float4*)(mu + n_base + nc);
                r4[j] = *(const float4*)(rs + n_base + nc);
            }
        }
    }

    unsigned long long acc[4][8];
    #pragma unroll
    for (int i = 0; i < 4; i++)
        #pragma unroll
        for (int j = 0; j < 8; j++) acc[i][j] = 0ULL;

    const int nstages = (K + 7) >> 3;
    float ra[NL];
    float4 rb[BSL];

    auto fetch = [&](int kg) {
        #pragma unroll
        for (int j = 0; j < NL; j++) {
            int i = tid + j * NT;
            int kk = i / BM, row = i % BM;
            int kkg = kg + kk;
            ra[j] = (m_base + row < M && kkg < K)
                  ? A[(long long)(m_base + row) * K + kkg] : 0.f;
        }
        #pragma unroll
        for (int j = 0; j < BSL; j++) {
            int s = tid + j * NT;
            if (s < 512) {
                int kb = kg + (s >> 6);
                int nc = (s & 63) * 4;
                if (kb < K) {
                    float4 v = *(const float4*)(B + (long long)kb * HW + n_base + nc);
                    if (LN) {
                        v.x = (v.x - m4[j].x) * r4[j].x; v.y = (v.y - m4[j].y) * r4[j].y;
                        v.z = (v.z - m4[j].z) * r4[j].z; v.w = (v.w - m4[j].w) * r4[j].w;
                    }
                    rb[j] = v;
                } else {
                    rb[j] = make_float4(0.f, 0.f, 0.f, 0.f);
                }
            }
        }
    };
    auto stash = [&](int buf) {
        #pragma unroll
        for (int j = 0; j < NL; j++) {
            int i = tid + j * NT;
            As[buf][i / BM][i % BM] = ra[j];
        }
        #pragma unroll
        for (int j = 0; j < BSL; j++) {
            int s = tid + j * NT;
            if (s < 512) *(float4*)&Bs[buf][s >> 6][(s & 63) * 4] = rb[j];
        }
    };

    fetch(0);
    stash(0);
    __syncthreads();

    for (int s = 0; s < nstages; s++) {
        int buf = s & 1;
        if (s + 1 < nstages) fetch((s + 1) * 8);
        #pragma unroll
        for (int kk = 0; kk < 8; kk++) {
            float4 av = *(const float4*)&As[buf][kk][ty * 4];
            unsigned long long bb[8];
            #pragma unroll
            for (int j = 0; j < 4; j++) {
                float4 bv = *(const float4*)&Bs[buf][kk][tx * 4 + 64 * j];
                bb[2 * j]     = pack2(bv.x, bv.y);
                bb[2 * j + 1] = pack2(bv.z, bv.w);
            }
            float am[4] = {av.x, av.y, av.z, av.w};
            #pragma unroll
            for (int i = 0; i < 4; i++) {
                unsigned long long ad = pack2(am[i], am[i]);
                #pragma unroll
                for (int j = 0; j < 8; j++) fma2(acc[i][j], ad, bb[j]);
            }
        }
        if (s + 1 < nstages) stash(buf ^ 1);
        __syncthreads();
    }

    if (EPI == 2) {
        // rows paired (2p = p1-row, 2p+1 = p2-row); gate -> C row mg/2
        #pragma unroll
        for (int p = 0; p < 2; p++) {
            int i0 = 2 * p;
            int mg = m_base + ty * 4 + i0;
            if (mg >= M) continue;
            float b1v = bias[mg], b2v = bias[mg + 1];
            float p1[16], p2[16];
            #pragma unroll
            for (int j = 0; j < 8; j++) {
                unpack2(acc[i0][j],     p1[2 * j], p1[2 * j + 1]);
                unpack2(acc[i0 + 1][j], p2[2 * j], p2[2 * j + 1]);
            }
            long long o = (long long)(mg >> 1) * HW + n_base + tx * 4;
            #pragma unroll
            for (int j = 0; j < 4; j++) {
                float4 v;
                v.x = gatef(p1[4 * j]     + b1v, p2[4 * j]     + b2v);
                v.y = gatef(p1[4 * j + 1] + b1v, p2[4 * j + 1] + b2v);
                v.z = gatef(p1[4 * j + 2] + b1v, p2[4 * j + 2] + b2v);
                v.w = gatef(p1[4 * j + 3] + b1v, p2[4 * j + 3] + b2v);
                *(float4*)(C + o + 64 * j) = v;
            }
        }
    } else {
        #pragma unroll
        for (int i = 0; i < 4; i++) {
            int mg = m_base + ty * 4 + i;
            if (mg >= M) continue;
            float bv = (EPI == 1) ? bias[mg] : 0.f;
            long long o = (long long)mg * HW + n_base + tx * 4;
            #pragma unroll
            for (int j = 0; j < 4; j++) {
                float4 v;
                unpack2(acc[i][2 * j],     v.x, v.y);
                unpack2(acc[i][2 * j + 1], v.z, v.w);
                if (EPI == 1) { v.x += bv; v.y += bv; v.z += bv; v.w += bv; }
                if (RESID) {
                    float4 rr = *(const float4*)(R + o + 64 * j);
                    v.x += rr.x; v.y += rr.y; v.z += rr.z; v.w += rr.w;
                }
                *(float4*)(C + o + 64 * j) = v;
            }
        }
    }
}

// ---------------- 3x3 depthwise conv, SAME zero padding ----------------
// 32x32 output tile, 256 threads (32x8), 4 consecutive rows per thread,
// register sliding window: 18 LDS -> 36 FMA -> 4 outputs.
__global__ __launch_bounds__(256) void dwconv3(const float* __restrict__ in,
                                               const float* __restrict__ w,
                                               float* __restrict__ out) {
    int zc = blockIdx.z;                 // b*288 + c
    int c = zc % 288;
    const float* src = in  + (long long)zc * HW;
    float*       dst = out + (long long)zc * HW;
    int ox = blockIdx.x * 32, oy = blockIdx.y * 32;
    __shared__ float s[34][34];
    int tid = threadIdx.y * 32 + threadIdx.x;
    #pragma unroll
    for (int it = 0; it < 5; it++) {
        int i = tid + it * 256;
        if (i < 34 * 34) {
            int r = i / 34, cc = i % 34;
            int gy = oy + r - 1, gx = ox + cc - 1;
            float v = 0.f;
            if (gy >= 0 && gy < 256 && gx >= 0 && gx < 256) v = src[gy * 256 + gx];
            s[r][cc] = v;
        }
    }
    __syncthreads();
    const float* wc = w + c * 9;
    float w00 = wc[0], w01 = wc[1], w02 = wc[2];
    float w10 = wc[3], w11 = wc[4], w12 = wc[5];
    float w20 = wc[6], w21 = wc[7], w22 = wc[8];
    int tx = threadIdx.x;
    int r0 = threadIdx.y * 4;
    float a[6][3];
    #pragma unroll
    for (int dr = 0; dr < 6; dr++) {
        a[dr][0] = s[r0 + dr][tx];
        a[dr][1] = s[r0 + dr][tx + 1];
        a[dr][2] = s[r0 + dr][tx + 2];
    }
    #pragma unroll
    for (int i = 0; i < 4; i++) {
        float r = w00 * a[i][0]     + w01 * a[i][1]     + w02 * a[i][2]
                + w10 * a[i + 1][0] + w11 * a[i + 1][1] + w12 * a[i + 1][2]
                + w20 * a[i + 2][0] + w21 * a[i + 2][1] + w22 * a[i + 2][2];
        dst[(oy + r0 + i) * 256 + ox + tx] = r;
    }
}

// ---------------- svp 1x1 conv ----------------
__global__ void svp_kernel(const float* __restrict__ fea, const float* __restrict__ w,
                           float* __restrict__ out) {
    int i = blockIdx.x * blockDim.x + threadIdx.x;
    if (i >= BATCH * HW) return;
    int b = i >> 16, pix = i & 65535;
    const float* f = fea + (long long)b * 3 * HW + pix;
    float f0 = f[0], f1 = f[HW], f2 = f[2 * HW];
    float* o = out + (long long)b * 12 * HW + pix;
    #pragma unroll
    for (int r = 0; r < 12; r++)
        o[(long long)r * HW] = w[r * 3] * f0 + w[r * 3 + 1] * f1 + w[r * 3 + 2] * f2;
}

// ---------------- per-row sum of squares (for L2 norms) ----------------
__global__ void sumsq_kernel(const float* __restrict__ qkvd, const float* __restrict__ svpq,
                             float* __restrict__ ss) {
    int bid = blockIdx.x;
    int b = bid / 204, r = bid % 204;
    const float* row = (r < 192) ? qkvd + ((long long)b * 288 + r) * HW
                                 : svpq + ((long long)b * 12 + (r - 192)) * HW;
    float acc = 0.f;
    for (int i = threadIdx.x * 4; i < HW; i += blockDim.x * 4) {
        float4 v = *(const float4*)(row + i);
        acc += v.x * v.x + v.y * v.y + v.z * v.z + v.w * v.w;
    }
    __shared__ float red[256];
    red[threadIdx.x] = acc;
    __syncthreads();
    for (int st = 128; st > 0; st >>= 1) {
        if (threadIdx.x < st) red[threadIdx.x] += red[threadIdx.x + st];
        __syncthreads();
    }
    if (threadIdx.x == 0) ss[bid] = red[0];
}

// ---------------- Gram partials ----------------
__global__ __launch_bounds__(672) void gram_kernel(const float* __restrict__ qkvd,
                                                   const float* __restrict__ svpq,
                                                   float* __restrict__ gp) {
    __shared__ float qs[27 * GPAD];
    __shared__ float ks[24 * GPAD];
    int seg = blockIdx.x;
    int bh  = blockIdx.y;
    int b = bh >> 2, h = bh & 3;
    int tid = threadIdx.x;
    int c = tid / 24, d = tid % 24;
    bool active = tid < 648;
    long long segoff = (long long)seg * (HW / NSEG);
    float acc = 0.f;

    for (int ch = 0; ch < HW / NSEG; ch += GCH) {
        for (int i = tid; i < 51 * (GCH / 4); i += 672) {
            int row = i / (GCH / 4), col4 = i % (GCH / 4);
            const float* src;
            float* dstb;
            if (row < 27) {
                src = (row < 24) ? qkvd + ((long long)b * 288 + h * 24 + row) * HW
                                 : svpq + ((long long)b * 12 + h * 3 + (row - 24)) * HW;
                dstb = qs + row * GPAD;
            } else {
                int rr = row - 27;
                src = qkvd + ((long long)b * 288 + 96 + h * 24 + rr) * HW;
                dstb = ks + rr * GPAD;
            }
            *(float4*)(dstb + col4 * 4) = *(const float4*)(src + segoff + ch + col4 * 4);
        }
        __syncthreads();
        if (active) {
            const float4* q4 = (const float4*)(qs + c * GPAD);
            const float4* k4 = (const float4*)(ks + d * GPAD);
            #pragma unroll 8
            for (int p = 0; p < GCH / 4; p++) {
                float4 qv = q4[p], kv = k4[p];
                acc += qv.x * kv.x + qv.y * kv.y + qv.z * kv.z + qv.w * kv.w;
            }
        }
        __syncthreads();
    }
    if (active) gp[((long long)seg * 16 + bh) * 648 + tid] = acc;
}

// ---------------- attn softmax + fold proj_out -> M[b] ----------------
__global__ void attnm_kernel(const float* __restrict__ gp, const float* __restrict__ ss,
                             const float* __restrict__ temp, const float* __restrict__ projw,
                             float* __restrict__ Mout) {
    int b = blockIdx.x;
    __shared__ float attn_s[4][27][24];
    int tid = threadIdx.x;
    if (tid < 108) {
        int h = tid / 27, c = tid % 27;
        float ssq = (c < 24) ? ss[b * 204 + h * 24 + c]
                             : ss[b * 204 + 192 + h * 3 + (c - 24)];
        float nq = fmaxf(sqrtf(ssq), 1e-12f);
        float t = temp[h];
        float row[24];
        #pragma unroll
        for (int d = 0; d < 24; d++) {
            float g = 0.f;
            for (int s = 0; s < NSEG; s++)
                g += gp[((long long)s * 16 + b * 4 + h) * 648 + c * 24 + d];
            float nk = fmaxf(sqrtf(ss[b * 204 + 96 + h * 24 + d]), 1e-12f);
            row[d] = g * t / (nq * nk);
        }
        float mx = row[0];
        #pragma unroll
        for (int d = 1; d < 24; d++) mx = fmaxf(mx, row[d]);
        float sum = 0.f;
        #pragma unroll
        for (int d = 0; d < 24; d++) { row[d] = expf(row[d] - mx); sum += row[d]; }
        float inv = 1.f / sum;
        #pragma unroll
        for (int d = 0; d < 24; d++) attn_s[h][c][d] = row[d] * inv;
    }
    __syncthreads();
    for (int e = tid; e < 96 * 96; e += blockDim.x) {
        int o = e / 96, col = e % 96;
        int h = col / 24, d = col % 24;
        float s = 0.f;
        #pragma unroll
        for (int c = 0; c < 27; c++)
            s += projw[o * 108 + h * 27 + c] * attn_s[h][c][d];
        Mout[b * 9216 + e] = s;
    }
}

// ---------------- launch ----------------
extern "C" void kernel_launch(void* const* d_in, const int* in_sizes, int n_in,
                              void* d_out, int out_size) {
    const float* x           = (const float*)d_in[0];
    const float* svp_fea     = (const float*)d_in[1];
    const float* n1w         = (const float*)d_in[2];
    const float* n1b         = (const float*)d_in[3];
    const float* qkv_w       = (const float*)d_in[4];
    const float* qkv_dw_w    = (const float*)d_in[5];
    const float* svp_w       = (const float*)d_in[6];
    const float* temperature = (const float*)d_in[7];
    const float* proj_out_w  = (const float*)d_in[8];
    const float* n2w         = (const float*)d_in[9];
    const float* n2b         = (const float*)d_in[10];
    const float* ffn1_w      = (const float*)d_in[11];
    const float* ffn2_w      = (const float*)d_in[12];
    const float* ffn_out_w   = (const float*)d_in[13];
    float* out = (float*)d_out;

    float *qkv, *qkvd, *svpq, *mu, *rs, *ss, *gp, *Mm, *Aq, *bq, *Ag, *bg;
    cudaGetSymbolAddress((void**)&qkv,  g_qkv);
    cudaGetSymbolAddress((void**)&qkvd, g_qkvd);
    cudaGetSymbolAddress((void**)&svpq, g_svpq);
    cudaGetSymbolAddress((void**)&mu,   g_mu);
    cudaGetSymbolAddress((void**)&rs,   g_rs);
    cudaGetSymbolAddress((void**)&ss,   g_ss);
    cudaGetSymbolAddress((void**)&gp,   g_gp);
    cudaGetSymbolAddress((void**)&Mm,   g_M);
    cudaGetSymbolAddress((void**)&Aq,   g_Aq);
    cudaGetSymbolAddress((void**)&bq,   g_bq);
    cudaGetSymbolAddress((void**)&Ag,   g_Ag);
    cudaGetSymbolAddress((void**)&bg,   g_bg);

    const int pixBlocks = (BATCH * HW + 255) / 256;

    // 0. fold LN weights into A matrices
    prep_kernel<<<798, 96>>>(qkv_w, n1w, n1b, ffn1_w, ffn2_w, n2w, n2b,
                             Aq, bq, Ag, bg);
    // 1. LN1 stats
    ln_stats<<<pixBlocks, 256>>>(x, mu, rs);
    // 2. qkv = Aq @ LN(x) + bq   (LN applied in B-load)  [M=288, exact 3x96 tiles]
    gemm_k<96, 384, 1, 1, 0><<<dim3(256, 3, BATCH), 384>>>(Aq, x, nullptr, qkv, bq, mu, rs,
        288, 96, 0, 96LL * HW, 0, 288LL * HW);
    // 3. depthwise 3x3 (32x32 tiles)
    dwconv3<<<dim3(8, 8, BATCH * 288), dim3(32, 8)>>>(qkv, qkv_dw_w, qkvd);
    // 4. svp_q
    svp_kernel<<<pixBlocks, 256>>>(svp_fea, svp_w, svpq);
    // 5. row sums of squares
    sumsq_kernel<<<BATCH * 204, 256>>>(qkvd, svpq, ss);
    // 6. Gram partials
    gram_kernel<<<dim3(NSEG, 16), 672>>>(qkvd, svpq, gp);
    // 7. softmax + fold proj_out -> M[b]
    attnm_kernel<<<BATCH, 128>>>(gp, ss, temperature, proj_out_w, Mm);
    // 8. x2 = x + M_b @ v -> out   [M=96 exact]
    gemm_k<96, 384, 0, 0, 1><<<dim3(256, 1, BATCH), 384>>>(Mm, qkvd + 192LL * HW, x, out,
        nullptr, nullptr, nullptr,
        96, 96, 9216, 288LL * HW, 96LL * HW, 96LL * HW);
    // 9. LN2 stats (on out)
    ln_stats<<<pixBlocks, 256>>>(out, mu, rs);
    // 10. interleaved ffn1/ffn2 GEMM, LN'd B, fused dual-gate -> g (qkv buffer)
    gemm_k<128, 512, 2, 1, 0><<<dim3(256, 4, BATCH), 512>>>(Ag, out, nullptr, qkv, bg, mu, rs,
        510, 96, 0, 96LL * HW, 0, 288LL * HW);
    // 11. out = out + ffn_out_w @ g   [M=96 exact, K=255]
    gemm_k<96, 384, 0, 0, 1><<<dim3(256, 1, BATCH), 384>>>(ffn_out_w, qkv, out, out,
        nullptr, nullptr, nullptr,
        96, 255, 0, 288LL * HW, 96LL * HW, 96LL * HW);
}

// round 8
// speedup vs baseline: 2.4884x; 1.4547x over previous
#include <cuda_runtime.h>
#include <cuda_bf16.h>
#include <math.h>
#include <stdint.h>

#define HW 65536
#define BATCH 4
#define NSEG 32
#define GCH 128
#define GPAD 140

// ---------------- static scratch ----------------
__device__ float g_qkv [(size_t)BATCH * 288 * HW];   // qkv pre-dwconv; later gated FFN 'g'
__device__ float g_qkvd[(size_t)BATCH * 288 * HW];   // qkv post-dwconv (q|k|v)
__device__ float g_svpq[(size_t)BATCH * 12  * HW];   // svp_q
__device__ float g_mu  [(size_t)BATCH * HW];
__device__ float g_rs  [(size_t)BATCH * HW];
__device__ float g_ss  [BATCH * 204];
__device__ float g_gp  [NSEG * 16 * 648];
__device__ __nv_bfloat16 g_Mh [BATCH * 96 * 96];     // fused proj_out@attn, bf16 hi/lo
__device__ __nv_bfloat16 g_Ml [BATCH * 96 * 96];
__device__ __nv_bfloat16 g_Aqh[288 * 96];            // qkv_w * ln1w split
__device__ __nv_bfloat16 g_Aql[288 * 96];
__device__ float g_bq  [288];
__device__ __nv_bfloat16 g_Agh[512 * 96];            // ffn1/ffn2 * ln2w, tile-paired rows
__device__ __nv_bfloat16 g_Agl[512 * 96];
__device__ float g_bg  [512];                        // [0..255]=p1 bias, [256..511]=p2 bias
__device__ __nv_bfloat16 g_Fh [96 * 256];            // ffn_out_w padded K=256
__device__ __nv_bfloat16 g_Fl [96 * 256];

// ---------------- helpers ----------------
__device__ __forceinline__ void bsplit(float v, __nv_bfloat16& h, __nv_bfloat16& l) {
    h = __float2bfloat16(v);
    l = __float2bfloat16(v - __bfloat162float(h));
}
__device__ __forceinline__ uint32_t s2u(const void* p) {
    return (uint32_t)__cvta_generic_to_shared(p);
}
__device__ __forceinline__ void ldsm4t(uint32_t* r, uint32_t addr) {
    asm volatile("ldmatrix.sync.aligned.m8n8.x4.trans.shared.b16 {%0,%1,%2,%3}, [%4];"
        : "=r"(r[0]), "=r"(r[1]), "=r"(r[2]), "=r"(r[3]) : "r"(addr));
}
__device__ __forceinline__ void mma_bf16(float* d, const uint32_t* a, const uint32_t* b) {
    asm volatile("mma.sync.aligned.m16n8k16.row.col.f32.bf16.bf16.f32 "
        "{%0,%1,%2,%3}, {%4,%5,%6,%7}, {%8,%9}, {%0,%1,%2,%3};"
        : "+f"(d[0]), "+f"(d[1]), "+f"(d[2]), "+f"(d[3])
        : "r"(a[0]), "r"(a[1]), "r"(a[2]), "r"(a[3]), "r"(b[0]), "r"(b[1]));
}
__device__ __forceinline__ float gatef(float a, float bb) {
    float sig = 1.f / (1.f + expf(-bb));
    float gel = 0.5f * a * (1.f + erff(a * 0.70710678118654752f));
    return a * sig + bb * gel;
}

// ---------------- prep: fold LN weights, split to bf16 hi/lo ----------------
__global__ void prep_kernel(const float* __restrict__ qkv_w,
                            const float* __restrict__ n1w, const float* __restrict__ n1b,
                            const float* __restrict__ ffn1_w, const float* __restrict__ ffn2_w,
                            const float* __restrict__ n2w, const float* __restrict__ n2b,
                            const float* __restrict__ ffn_out_w) {
    int r = blockIdx.x;
    int k = threadIdx.x;  // 0..95
    __shared__ float red[96];
    if (r < 288) {
        float wv = qkv_w[r * 96 + k];
        bsplit(wv * n1w[k], g_Aqh[r * 96 + k], g_Aql[r * 96 + k]);
        red[k] = wv * n1b[k];
        __syncthreads();
        if (k == 0) { float s = 0.f; for (int j = 0; j < 96; j++) s += red[j]; g_bq[r] = s; }
    } else if (r < 800) {
        int c = r - 288;                  // 0..511
        int T = c >> 4, wi = c & 15;
        int g = T * 8 + (wi & 7);
        bool valid = (g < 255);
        const float* W = (wi < 8) ? ffn1_w : ffn2_w;
        float wv = valid ? W[g * 96 + k] : 0.f;
        bsplit(wv * n2w[k], g_Agh[c * 96 + k], g_Agl[c * 96 + k]);
        red[k] = wv * n2b[k];
        __syncthreads();
        if (k == 0) {
            float s = 0.f; for (int j = 0; j < 96; j++) s += red[j];
            if (valid) g_bg[(wi < 8 ? 0 : 256) + g] = s;
        }
    } else {
        int o = r - 800;                  // 0..95
        for (int kk = k; kk < 256; kk += 96) {
            float v = (kk < 255) ? ffn_out_w[o * 255 + kk] : 0.f;
            bsplit(v, g_Fh[o * 256 + kk], g_Fl[o * 256 + kk]);
        }
    }
}

// ---------------- LN stats ----------------
__global__ void ln_stats(const float* __restrict__ x, float* __restrict__ mu,
                         float* __restrict__ rs) {
    int i = blockIdx.x * blockDim.x + threadIdx.x;
    if (i >= BATCH * HW) return;
    int b = i >> 16, pix = i & 65535;
    const float* xp = x + (long long)b * 96 * HW + pix;
    float sum = 0.f, sq = 0.f;
    #pragma unroll 8
    for (int c = 0; c < 96; c++) {
        float v = xp[(long long)c * HW];
        sum += v; sq += v * v;
    }
    float m = sum * (1.f / 96.f);
    float var = sq * (1.f / 96.f) - m * m;
    mu[i] = m;
    rs[i] = rsqrtf(var + 1e-5f);
}

// ---------------- tensor-core GEMM: C[M,N=65536] = A[M,K]@B[K,N], split-bf16 ----------------
// BM=BN=128, BK=32, 256 threads (4x2 warps of 32x64).
// EPI: 0 plain(+RESID), 1 +bias, 2 dual-gate (m16 tile rows r/r+8 = p1/p2 -> out row T*8+r)
template <int EPI, int LN, int RESID>
__global__ __launch_bounds__(256) void gemm_t(
    const __nv_bfloat16* __restrict__ Ah, const __nv_bfloat16* __restrict__ Al,
    const float* __restrict__ B, const float* __restrict__ R, float* __restrict__ C,
    const float* __restrict__ bias,
    const float* __restrict__ mu, const float* __restrict__ rs,
    int M, int K, int Kpad,
    long long sA, long long sB, long long sR, long long sC)
{
    extern __shared__ __align__(16) char smem_raw[];
    __nv_bfloat16* Ash = (__nv_bfloat16*)smem_raw;       // [2][32][136]
    __nv_bfloat16* Asl = Ash + 2 * 4352;
    __nv_bfloat16* Bsh = Asl + 2 * 4352;
    __nv_bfloat16* Bsl = Bsh + 2 * 4352;

    Ah += (long long)blockIdx.z * sA;
    Al += (long long)blockIdx.z * sA;
    B  += (long long)blockIdx.z * sB;
    C  += (long long)blockIdx.z * sC;
    if (RESID) R += (long long)blockIdx.z * sR;
    if (LN) { mu += (long long)blockIdx.z * HW; rs += (long long)blockIdx.z * HW; }

    const int m_base = blockIdx.y * 128;
    const int n_base = blockIdx.x * 128;
    const int tid  = threadIdx.x;
    const int lane = tid & 31;
    const int warp = tid >> 5;
    const int wm = warp >> 1, wn = warp & 1;

    // loader coords
    const int bcol = (tid & 31) * 4;   // B col (fixed)
    const int bk0  = tid >> 5;         // B k row base (+8j)
    const int am   = tid & 127;        // A m (fixed)
    const int akc0 = tid >> 7;         // A k-chunk base (+2j), chunk = 8 bf16

    float4 m4, r4;
    if (LN) {
        m4 = *(const float4*)(mu + n_base + bcol);
        r4 = *(const float4*)(rs + n_base + bcol);
    }

    float acc[2][8][4];
    #pragma unroll
    for (int i = 0; i < 2; i++)
        #pragma unroll
        for (int j = 0; j < 8; j++)
            #pragma unroll
            for (int q = 0; q < 4; q++) acc[i][j][q] = 0.f;

    const int nst = (K + 31) >> 5;
    uint4 rgah[2], rgal[2];
    float4 rgb[4];

    // ldmatrix lane-derived offsets
    const int a_row = (lane & 7) + ((lane >> 4) & 1) * 8;
    const int a_col = ((lane >> 3) & 1) * 8;
    const int b_row = (lane & 7) + ((lane >> 3) & 1) * 8;
    const int b_col = ((lane >> 4) & 1) * 8 + wn * 64;

    auto fetch = [&](int kg) {
        #pragma unroll
        for (int j = 0; j < 2; j++) {
            int kc = akc0 + 2 * j;
            int grow = m_base + am;
            if (grow < M) {
                long long off = (long long)grow * Kpad + kg + kc * 8;
                rgah[j] = *(const uint4*)(Ah + off);
                rgal[j] = *(const uint4*)(Al + off);
            } else {
                rgah[j] = make_uint4(0, 0, 0, 0);
                rgal[j] = make_uint4(0, 0, 0, 0);
            }
        }
        #pragma unroll
        for (int j = 0; j < 4; j++) {
            int kb = kg + bk0 + 8 * j;
            if (kb < K) {
                float4 v = *(const float4*)(B + (long long)kb * HW + n_base + bcol);
                if (LN) {
                    v.x = (v.x - m4.x) * r4.x; v.y = (v.y - m4.y) * r4.y;
                    v.z = (v.z - m4.z) * r4.z; v.w = (v.w - m4.w) * r4.w;
                }
                rgb[j] = v;
            } else {
                rgb[j] = make_float4(0.f, 0.f, 0.f, 0.f);
            }
        }
    };
    auto stash = [&](int buf) {
        int base = buf * 4352;
        #pragma unroll
        for (int j = 0; j < 2; j++) {
            int kb = (akc0 + 2 * j) * 8;
            const __nv_bfloat16* ph = (const __nv_bfloat16*)&rgah[j];
            const __nv_bfloat16* pl = (const __nv_bfloat16*)&rgal[j];
            #pragma unroll
            for (int rr = 0; rr < 8; rr++) {
                Ash[base + (kb + rr) * 136 + am] = ph[rr];
                Asl[base + (kb + rr) * 136 + am] = pl[rr];
            }
        }
        #pragma unroll
        for (int j = 0; j < 4; j++) {
            int kb = bk0 + 8 * j;
            float* pv = (float*)&rgb[j];
            __nv_bfloat16 h0, h1, h2, h3, l0, l1, l2, l3;
            bsplit(pv[0], h0, l0); bsplit(pv[1], h1, l1);
            bsplit(pv[2], h2, l2); bsplit(pv[3], h3, l3);
            __nv_bfloat162* dh = (__nv_bfloat162*)&Bsh[base + kb * 136 + bcol];
            __nv_bfloat162* dl = (__nv_bfloat162*)&Bsl[base + kb * 136 + bcol];
            dh[0] = __nv_bfloat162(h0, h1); dh[1] = __nv_bfloat162(h2, h3);
            dl[0] = __nv_bfloat162(l0, l1); dl[1] = __nv_bfloat162(l2, l3);
        }
    };

    fetch(0);
    stash(0);
    __syncthreads();

    for (int s = 0; s < nst; s++) {
        int buf = s & 1;
        if (s + 1 < nst) fetch((s + 1) * 32);

        int base = buf * 4352;
        #pragma unroll
        for (int step = 0; step < 2; step++) {
            int k0 = step * 16;
            uint32_t ah[2][4], al[2][4];
            #pragma unroll
            for (int i = 0; i < 2; i++) {
                int col = wm * 32 + i * 16 + a_col;
                int off = base + (k0 + a_row) * 136 + col;
                ldsm4t(ah[i], s2u(&Ash[off]));
                ldsm4t(al[i], s2u(&Asl[off]));
            }
            uint32_t bh[4][4], bl[4][4];
            #pragma unroll
            for (int jp = 0; jp < 4; jp++) {
                int col = b_col + jp * 16;
                int off = base + (k0 + b_row) * 136 + col;
                ldsm4t(bh[jp], s2u(&Bsh[off]));
                ldsm4t(bl[jp], s2u(&Bsl[off]));
            }
            #pragma unroll
            for (int i = 0; i < 2; i++) {
                #pragma unroll
                for (int j = 0; j < 8; j++) {
                    int jp = j >> 1;
                    const uint32_t* bhp = (j & 1) ? bh[jp] + 2 : bh[jp];
                    const uint32_t* blp = (j & 1) ? bl[jp] + 2 : bl[jp];
                    mma_bf16(acc[i][j], ah[i], bhp);
                    mma_bf16(acc[i][j], ah[i], blp);
                    mma_bf16(acc[i][j], al[i], bhp);
                }
            }
        }
        if (s + 1 < nst) stash(buf ^ 1);
        __syncthreads();
    }

    // ---------------- epilogue ----------------
    if (EPI == 2) {
        #pragma unroll
        for (int i = 0; i < 2; i++) {
            int T = (m_base >> 4) + wm * 2 + i;
            int g = T * 8 + (lane >> 2);
            if (g < 255) {
                float b1 = bias[g], b2 = bias[256 + g];
                #pragma unroll
                for (int j = 0; j < 8; j++) {
                    int col = n_base + wn * 64 + j * 8 + 2 * (lane & 3);
                    float2 v;
                    v.x = gatef(acc[i][j][0] + b1, acc[i][j][2] + b2);
                    v.y = gatef(acc[i][j][1] + b1, acc[i][j][3] + b2);
                    *(float2*)(C + (long long)g * HW + col) = v;
                }
            }
        }
    } else {
        #pragma unroll
        for (int i = 0; i < 2; i++) {
            int r0 = m_base + wm * 32 + i * 16 + (lane >> 2);
            int r1 = r0 + 8;
            float bv0 = 0.f, bv1 = 0.f;
            if (EPI == 1) {
                if (r0 < M) bv0 = bias[r0];
                if (r1 < M) bv1 = bias[r1];
            }
            #pragma unroll
            for (int j = 0; j < 8; j++) {
                int col = n_base + wn * 64 + j * 8 + 2 * (lane & 3);
                if (r0 < M) {
                    float2 v = make_float2(acc[i][j][0] + bv0, acc[i][j][1] + bv0);
                    long long o = (long long)r0 * HW + col;
                    if (RESID) { float2 rr = *(const float2*)(R + o); v.x += rr.x; v.y += rr.y; }
                    *(float2*)(C + o) = v;
                }
                if (r1 < M) {
                    float2 v = make_float2(acc[i][j][2] + bv1, acc[i][j][3] + bv1);
                    long long o = (long long)r1 * HW + col;
                    if (RESID) { float2 rr = *(const float2*)(R + o); v.x += rr.x; v.y += rr.y; }
                    *(float2*)(C + o) = v;
                }
            }
        }
    }
}

// ---------------- 3x3 depthwise conv ----------------
__global__ __launch_bounds__(256) void dwconv3(const float* __restrict__ in,
                                               const float* __restrict__ w,
                                               float* __restrict__ out) {
    int zc = blockIdx.z;
    int c = zc % 288;
    const float* src = in  + (long long)zc * HW;
    float*       dst = out + (long long)zc * HW;
    int ox = blockIdx.x * 32, oy = blockIdx.y * 32;
    __shared__ float s[34][34];
    int tid = threadIdx.y * 32 + threadIdx.x;
    #pragma unroll
    for (int it = 0; it < 5; it++) {
        int i = tid + it * 256;
        if (i < 34 * 34) {
            int r = i / 34, cc = i % 34;
            int gy = oy + r - 1, gx = ox + cc - 1;
            float v = 0.f;
            if (gy >= 0 && gy < 256 && gx >= 0 && gx < 256) v = src[gy * 256 + gx];
            s[r][cc] = v;
        }
    }
    __syncthreads();
    const float* wc = w + c * 9;
    float w00 = wc[0], w01 = wc[1], w02 = wc[2];
    float w10 = wc[3], w11 = wc[4], w12 = wc[5];
    float w20 = wc[6], w21 = wc[7], w22 = wc[8];
    int tx = threadIdx.x;
    int r0 = threadIdx.y * 4;
    float a[6][3];
    #pragma unroll
    for (int dr = 0; dr < 6; dr++) {
        a[dr][0] = s[r0 + dr][tx];
        a[dr][1] = s[r0 + dr][tx + 1];
        a[dr][2] = s[r0 + dr][tx + 2];
    }
    #pragma unroll
    for (int i = 0; i < 4; i++) {
        float r = w00 * a[i][0]     + w01 * a[i][1]     + w02 * a[i][2]
                + w10 * a[i + 1][0] + w11 * a[i + 1][1] + w12 * a[i + 1][2]
                + w20 * a[i + 2][0] + w21 * a[i + 2][1] + w22 * a[i + 2][2];
        dst[(oy + r0 + i) * 256 + ox + tx] = r;
    }
}

// ---------------- svp 1x1 conv ----------------
__global__ void svp_kernel(const float* __restrict__ fea, const float* __restrict__ w,
                           float* __restrict__ out) {
    int i = blockIdx.x * blockDim.x + threadIdx.x;
    if (i >= BATCH * HW) return;
    int b = i >> 16, pix = i & 65535;
    const float* f = fea + (long long)b * 3 * HW + pix;
    float f0 = f[0], f1 = f[HW], f2 = f[2 * HW];
    float* o = out + (long long)b * 12 * HW + pix;
    #pragma unroll
    for (int r = 0; r < 12; r++)
        o[(long long)r * HW] = w[r * 3] * f0 + w[r * 3 + 1] * f1 + w[r * 3 + 2] * f2;
}

// ---------------- per-row sum of squares ----------------
__global__ void sumsq_kernel(const float* __restrict__ qkvd, const float* __restrict__ svpq,
                             float* __restrict__ ss) {
    int bid = blockIdx.x;
    int b = bid / 204, r = bid % 204;
    const float* row = (r < 192) ? qkvd + ((long long)b * 288 + r) * HW
                                 : svpq + ((long long)b * 12 + (r - 192)) * HW;
    float acc = 0.f;
    for (int i = threadIdx.x * 4; i < HW; i += blockDim.x * 4) {
        float4 v = *(const float4*)(row + i);
        acc += v.x * v.x + v.y * v.y + v.z * v.z + v.w * v.w;
    }
    __shared__ float red[256];
    red[threadIdx.x] = acc;
    __syncthreads();
    for (int st = 128; st > 0; st >>= 1) {
        if (threadIdx.x < st) red[threadIdx.x] += red[threadIdx.x + st];
        __syncthreads();
    }
    if (threadIdx.x == 0) ss[bid] = red[0];
}

// ---------------- Gram partials ----------------
__global__ __launch_bounds__(672) void gram_kernel(const float* __restrict__ qkvd,
                                                   const float* __restrict__ svpq,
                                                   float* __restrict__ gp) {
    __shared__ float qs[27 * GPAD];
    __shared__ float ks[24 * GPAD];
    int seg = blockIdx.x;
    int bh  = blockIdx.y;
    int b = bh >> 2, h = bh & 3;
    int tid = threadIdx.x;
    int c = tid / 24, d = tid % 24;
    bool active = tid < 648;
    long long segoff = (long long)seg * (HW / NSEG);
    float acc = 0.f;

    for (int ch = 0; ch < HW / NSEG; ch += GCH) {
        for (int i = tid; i < 51 * (GCH / 4); i += 672) {
            int row = i / (GCH / 4), col4 = i % (GCH / 4);
            const float* src;
            float* dstb;
            if (row < 27) {
                src = (row < 24) ? qkvd + ((long long)b * 288 + h * 24 + row) * HW
                                 : svpq + ((long long)b * 12 + h * 3 + (row - 24)) * HW;
                dstb = qs + row * GPAD;
            } else {
                int rr = row - 27;
                src = qkvd + ((long long)b * 288 + 96 + h * 24 + rr) * HW;
                dstb = ks + rr * GPAD;
            }
            *(float4*)(dstb + col4 * 4) = *(const float4*)(src + segoff + ch + col4 * 4);
        }
        __syncthreads();
        if (active) {
            const float4* q4 = (const float4*)(qs + c * GPAD);
            const float4* k4 = (const float4*)(ks + d * GPAD);
            #pragma unroll 8
            for (int p = 0; p < GCH / 4; p++) {
                float4 qv = q4[p], kv = k4[p];
                acc += qv.x * kv.x + qv.y * kv.y + qv.z * kv.z + qv.w * kv.w;
            }
        }
        __syncthreads();
    }
    if (active) gp[((long long)seg * 16 + bh) * 648 + tid] = acc;
}

// ---------------- attn softmax + fold proj_out -> M[b] (bf16 split) ----------------
__global__ void attnm_kernel(const float* __restrict__ gp, const float* __restrict__ ss,
                             const float* __restrict__ temp, const float* __restrict__ projw,
                             __nv_bfloat16* __restrict__ Mh, __nv_bfloat16* __restrict__ Ml) {
    int b = blockIdx.x;
    __shared__ float attn_s[4][27][24];
    int tid = threadIdx.x;
    if (tid < 108) {
        int h = tid / 27, c = tid % 27;
        float ssq = (c < 24) ? ss[b * 204 + h * 24 + c]
                             : ss[b * 204 + 192 + h * 3 + (c - 24)];
        float nq = fmaxf(sqrtf(ssq), 1e-12f);
        float t = temp[h];
        float row[24];
        #pragma unroll
        for (int d = 0; d < 24; d++) {
            float g = 0.f;
            for (int s = 0; s < NSEG; s++)
                g += gp[((long long)s * 16 + b * 4 + h) * 648 + c * 24 + d];
            float nk = fmaxf(sqrtf(ss[b * 204 + 96 + h * 24 + d]), 1e-12f);
            row[d] = g * t / (nq * nk);
        }
        float mx = row[0];
        #pragma unroll
        for (int d = 1; d < 24; d++) mx = fmaxf(mx, row[d]);
        float sum = 0.f;
        #pragma unroll
        for (int d = 0; d < 24; d++) { row[d] = expf(row[d] - mx); sum += row[d]; }
        float inv = 1.f / sum;
        #pragma unroll
        for (int d = 0; d < 24; d++) attn_s[h][c][d] = row[d] * inv;
    }
    __syncthreads();
    for (int e = tid; e < 96 * 96; e += blockDim.x) {
        int o = e / 96, col = e % 96;
        int h = col / 24, d = col % 24;
        float s = 0.f;
        #pragma unroll
        for (int c = 0; c < 27; c++)
            s += projw[o * 108 + h * 27 + c] * attn_s[h][c][d];
        bsplit(s, Mh[b * 9216 + e], Ml[b * 9216 + e]);
    }
}

// ---------------- launch ----------------
extern "C" void kernel_launch(void* const* d_in, const int* in_sizes, int n_in,
                              void* d_out, int out_size) {
    const float* x           = (const float*)d_in[0];
    const float* svp_fea     = (const float*)d_in[1];
    const float* n1w         = (const float*)d_in[2];
    const float* n1b         = (const float*)d_in[3];
    const float* qkv_w       = (const float*)d_in[4];
    const float* qkv_dw_w    = (const float*)d_in[5];
    const float* svp_w       = (const float*)d_in[6];
    const float* temperature = (const float*)d_in[7];
    const float* proj_out_w  = (const float*)d_in[8];
    const float* n2w         = (const float*)d_in[9];
    const float* n2b         = (const float*)d_in[10];
    const float* ffn1_w      = (const float*)d_in[11];
    const float* ffn2_w      = (const float*)d_in[12];
    const float* ffn_out_w   = (const float*)d_in[13];
    float* out = (float*)d_out;

    float *qkv, *qkvd, *svpq, *mu, *rs, *ss, *gp, *bq, *bg;
    __nv_bfloat16 *Mh, *Ml, *Aqh, *Aql, *Agh, *Agl, *Fh, *Fl;
    cudaGetSymbolAddress((void**)&qkv,  g_qkv);
    cudaGetSymbolAddress((void**)&qkvd, g_qkvd);
    cudaGetSymbolAddress((void**)&svpq, g_svpq);
    cudaGetSymbolAddress((void**)&mu,   g_mu);
    cudaGetSymbolAddress((void**)&rs,   g_rs);
    cudaGetSymbolAddress((void**)&ss,   g_ss);
    cudaGetSymbolAddress((void**)&gp,   g_gp);
    cudaGetSymbolAddress((void**)&Mh,   g_Mh);
    cudaGetSymbolAddress((void**)&Ml,   g_Ml);
    cudaGetSymbolAddress((void**)&Aqh,  g_Aqh);
    cudaGetSymbolAddress((void**)&Aql,  g_Aql);
    cudaGetSymbolAddress((void**)&bq,   g_bq);
    cudaGetSymbolAddress((void**)&Agh,  g_Agh);
    cudaGetSymbolAddress((void**)&Agl,  g_Agl);
    cudaGetSymbolAddress((void**)&bg,   g_bg);
    cudaGetSymbolAddress((void**)&Fh,   g_Fh);
    cudaGetSymbolAddress((void**)&Fl,   g_Fl);

    const int GEMM_SMEM = 4 * 2 * 32 * 136 * 2;   // 69632 bytes
    cudaFuncSetAttribute(gemm_t<1, 1, 0>, cudaFuncAttributeMaxDynamicSharedMemorySize, GEMM_SMEM);
    cudaFuncSetAttribute(gemm_t<0, 0, 1>, cudaFuncAttributeMaxDynamicSharedMemorySize, GEMM_SMEM);
    cudaFuncSetAttribute(gemm_t<2, 1, 0>, cudaFuncAttributeMaxDynamicSharedMemorySize, GEMM_SMEM);

    const int pixBlocks = (BATCH * HW + 255) / 256;

    // 0. fold LN weights into split-bf16 A matrices
    prep_kernel<<<896, 96>>>(qkv_w, n1w, n1b, ffn1_w, ffn2_w, n2w, n2b, ffn_out_w);
    // 1. LN1 stats
    ln_stats<<<pixBlocks, 256>>>(x, mu, rs);
    // 2. qkv = Aq @ LN(x) + bq
    gemm_t<1, 1, 0><<<dim3(512, 3, BATCH), 256, GEMM_SMEM>>>(Aqh, Aql, x, nullptr, qkv,
        bq, mu, rs, 288, 96, 96, 0, 96LL * HW, 0, 288LL * HW);
    // 3. depthwise 3x3
    dwconv3<<<dim3(8, 8, BATCH * 288), dim3(32, 8)>>>(qkv, qkv_dw_w, qkvd);
    // 4. svp_q
    svp_kernel<<<pixBlocks, 256>>>(svp_fea, svp_w, svpq);
    // 5. row sums of squares
    sumsq_kernel<<<BATCH * 204, 256>>>(qkvd, svpq, ss);
    // 6. Gram partials
    gram_kernel<<<dim3(NSEG, 16), 672>>>(qkvd, svpq, gp);
    // 7. softmax + fold proj_out -> M[b] (bf16 split)
    attnm_kernel<<<BATCH, 128>>>(gp, ss, temperature, proj_out_w, Mh, Ml);
    // 8. x2 = x + M_b @ v -> out
    gemm_t<0, 0, 1><<<dim3(512, 1, BATCH), 256, GEMM_SMEM>>>(Mh, Ml, qkvd + 192LL * HW, x, out,
        nullptr, nullptr, nullptr, 96, 96, 96, 9216, 288LL * HW, 96LL * HW, 96LL * HW);
    // 9. LN2 stats
    ln_stats<<<pixBlocks, 256>>>(out, mu, rs);
    // 10. interleaved ffn1/ffn2 GEMM + fused dual-gate -> g (qkv buffer)
    gemm_t<2, 1, 0><<<dim3(512, 4, BATCH), 256, GEMM_SMEM>>>(Agh, Agl, out, nullptr, qkv,
        bg, mu, rs, 512, 96, 96, 0, 96LL * HW, 0, 288LL * HW);
    // 11. out = out + ffn_out_w @ g
    gemm_t<0, 0, 1><<<dim3(512, 1, BATCH), 256, GEMM_SMEM>>>(Fh, Fl, qkv, out, out,
        nullptr, nullptr, nullptr, 96, 255, 256, 0, 288LL * HW, 96LL * HW, 96LL * HW);
}